// round 13
// baseline (speedup 1.0000x reference)
#include <cuda_runtime.h>
#include <cuda_bf16.h>
#include <math.h>

#define NN 50000
#define NE 800000
#define DI 64
#define DH 256

// ---------------- scratch (device globals) -----------------------------------
__device__ float g_xl[NN * DH];     // xs @ W_lin + b_lin
__device__ __align__(16) __nv_bfloat16 g_xsh[NN * DI];   // xs hi  [row][k]
__device__ __align__(16) __nv_bfloat16 g_xsl[NN * DI];   // xs lo
__device__ __align__(16) __nv_bfloat16 g_xah[NN * DI];   // xagg hi [row][k]
__device__ __align__(16) __nv_bfloat16 g_xal[NN * DI];
__device__ __align__(16) __nv_bfloat16 g_zh[NN * DH];    // z hi [row][k]
__device__ __align__(16) __nv_bfloat16 g_zl[NN * DH];
__device__ __align__(16) __nv_bfloat16 g_wch[DH * DI];   // W_gcn  [col][k]
__device__ __align__(16) __nv_bfloat16 g_wcl[DH * DI];
__device__ __align__(16) __nv_bfloat16 g_wlh[DH * DI];   // W_lin  [col][k]
__device__ __align__(16) __nv_bfloat16 g_wll[DH * DI];
__device__ __align__(16) __nv_bfloat16 g_wgh[DH * DH];   // W_gate [col][k]
__device__ __align__(16) __nv_bfloat16 g_wgl[DH * DH];
__device__ int   g_deg[NN];
__device__ float g_dinv[NN];
__device__ int   g_rowptr[NN + 1];
__device__ int   g_fill[NN];
__device__ int   g_srcsorted[NE];
__device__ float g_colsum[DH];
__device__ float g_colsq[DH];
__device__ float g_scale[DH];
__device__ float g_shift[DH];
__device__ int   g_is64;

__device__ __forceinline__ void bsplit(float x, __nv_bfloat16& h, __nv_bfloat16& l) {
    h = __float2bfloat16(x);
    l = __float2bfloat16(x - __bfloat162float(h));
}

// ---------------- small kernels ----------------------------------------------
__global__ void init_kernel() {
    int i = blockIdx.x * blockDim.x + threadIdx.x;
    if (i < NN) { g_deg[i] = 0; g_fill[i] = 0; }
    if (i < DH) { g_colsum[i] = 0.f; g_colsq[i] = 0.f; }
}

__global__ void detect_kernel(const void* ei) {
    if (threadIdx.x == 0 && blockIdx.x == 0) {
        const long long* p = (const long long*)ei;
        int ok = 1;
        for (int i = 0; i < 64; i++) {
            long long v = p[i];
            if (v < 0 || v >= NN) ok = 0;
        }
        g_is64 = ok;
    }
}

__device__ __forceinline__ int load_edge(const void* ei, int pos, int is64) {
    return is64 ? (int)((const long long*)ei)[pos] : ((const int*)ei)[pos];
}

__global__ void deg_kernel(const void* __restrict__ ei) {
    int e = blockIdx.x * blockDim.x + threadIdx.x;
    if (e >= NE) return;
    int d = load_edge(ei, NE + e, g_is64);
    atomicAdd(&g_deg[d], 1);
}

__global__ void dinv_kernel() {
    int i = blockIdx.x * blockDim.x + threadIdx.x;
    if (i < NN) g_dinv[i] = rsqrtf((float)(g_deg[i] + 1));
}

__global__ void scan_kernel() {
    __shared__ int s[1024];
    int t = threadIdx.x;
    const int C = (NN + 1023) / 1024;
    int start = t * C;
    int end = min(start + C, NN);
    int sum = 0;
    for (int i = start; i < end; i++) sum += g_deg[i];
    s[t] = sum;
    __syncthreads();
    for (int off = 1; off < 1024; off <<= 1) {
        int v = (t >= off) ? s[t - off] : 0;
        __syncthreads();
        s[t] += v;
        __syncthreads();
    }
    int run = s[t] - sum;
    for (int i = start; i < end; i++) { g_rowptr[i] = run; run += g_deg[i]; }
    if (t == 0) g_rowptr[NN] = s[1023];
}

__global__ void scatter_kernel(const void* __restrict__ ei) {
    int e = blockIdx.x * blockDim.x + threadIdx.x;
    if (e >= NE) return;
    int is64 = g_is64;
    int d = load_edge(ei, NE + e, is64);
    int srcv = load_edge(ei, e, is64);
    int pos = g_rowptr[d] + atomicAdd(&g_fill[d], 1);
    g_srcsorted[pos] = srcv;
}

// ---------------- weight / input pre-splitting -------------------------------
__global__ void wsplit_kernel(const float* __restrict__ Wc,
                              const float* __restrict__ Wl,
                              const float* __restrict__ Wg) {
    int i = blockIdx.x * blockDim.x + threadIdx.x;
    const int NW1 = DH * DI;
    if (i < 2 * NW1) {
        int sel = i / NW1;
        int j = i - sel * NW1;
        int c = j / DI, k = j - c * DI;
        float x = (sel ? Wl : Wc)[k * DH + c];
        __nv_bfloat16 h, l;
        bsplit(x, h, l);
        if (sel) { g_wlh[j] = h; g_wll[j] = l; }
        else     { g_wch[j] = h; g_wcl[j] = l; }
    } else {
        int j = i - 2 * NW1;
        if (j >= DH * DH) return;
        int c = j / DH, k = j - c * DH;
        float x = Wg[k * DH + c];
        __nv_bfloat16 h, l;
        bsplit(x, h, l);
        g_wgh[j] = h; g_wgl[j] = l;
    }
}

__global__ void xsplit_kernel(const float* __restrict__ xs) {
    int i = blockIdx.x * blockDim.x + threadIdx.x;  // float4 index
    if (i >= NN * DI / 4) return;
    float4 v = ((const float4*)xs)[i];
    __nv_bfloat162 h0, l0, h1, l1;
    bsplit(v.x, h0.x, l0.x); bsplit(v.y, h0.y, l0.y);
    bsplit(v.z, h1.x, l1.x); bsplit(v.w, h1.y, l1.y);
    ((__nv_bfloat162*)g_xsh)[i * 2] = h0;
    ((__nv_bfloat162*)g_xsh)[i * 2 + 1] = h1;
    ((__nv_bfloat162*)g_xsl)[i * 2] = l0;
    ((__nv_bfloat162*)g_xsl)[i * 2 + 1] = l1;
}

// ---------------- 64-dim aggregation (warp per node, CSR) --------------------
__global__ __launch_bounds__(256) void aggx_kernel(const float* __restrict__ xs) {
    int w = (blockIdx.x * 256 + threadIdx.x) >> 5;
    int lane = threadIdx.x & 31;
    if (w >= NN) return;
    int beg = g_rowptr[w];
    int end = g_rowptr[w + 1];
    const float2* xs2 = (const float2*)xs;
    float2 acc = make_float2(0.f, 0.f);
    for (int k = beg; k < end; k++) {
        int s = g_srcsorted[k];
        float wt = g_dinv[s];
        float2 v = xs2[s * 32 + lane];
        acc.x += v.x * wt;
        acc.y += v.y * wt;
    }
    float di = g_dinv[w];
    float2 xv = xs2[w * 32 + lane];
    float rx = acc.x * di + xv.x * di * di;
    float ry = acc.y * di + xv.y * di * di;
    __nv_bfloat162 h2, l2;
    bsplit(rx, h2.x, l2.x);
    bsplit(ry, h2.y, l2.y);
    ((__nv_bfloat162*)g_xah)[w * 32 + lane] = h2;
    ((__nv_bfloat162*)g_xal)[w * 32 + lane] = l2;
}

// ---------------- bf16 split-3 tensor-core GEMM (ldmatrix) -------------------
// C[M x 256] = A[M x KDIM] @ W[KDIM x 256]
// EPI 0: z = tanh(acc + b_gcn) -> g_zh/g_zl bf16 split (no fp32 buffer)
// EPI 1: C = acc + bias                                  (xl)
// EPI 2: g = sigmoid(acc + b_gate); C = relu((1-g)*xl + g*(zh+zl))
//        + fused BN column statistics

__device__ __forceinline__ void mma_bf16(float c[4], const unsigned a[4],
                                         unsigned b0, unsigned b1) {
    asm volatile(
        "mma.sync.aligned.m16n8k16.row.col.f32.bf16.bf16.f32 "
        "{%0,%1,%2,%3},{%4,%5,%6,%7},{%8,%9},{%0,%1,%2,%3};\n"
        : "+f"(c[0]), "+f"(c[1]), "+f"(c[2]), "+f"(c[3])
        : "r"(a[0]), "r"(a[1]), "r"(a[2]), "r"(a[3]), "r"(b0), "r"(b1));
}

__device__ __forceinline__ void ldsm_x4(unsigned r[4], unsigned addr) {
    asm volatile("ldmatrix.sync.aligned.m8n8.x4.shared.b16 {%0,%1,%2,%3}, [%4];"
        : "=r"(r[0]), "=r"(r[1]), "=r"(r[2]), "=r"(r[3]) : "r"(addr));
}

__device__ __forceinline__ void ldsm_x2(unsigned& r0, unsigned& r1, unsigned addr) {
    asm volatile("ldmatrix.sync.aligned.m8n8.x2.shared.b16 {%0,%1}, [%2];"
        : "=r"(r0), "=r"(r1) : "r"(addr));
}

#define SSTR 40   // smem row stride in bf16 elems; r*20 mod 32 covers all banks

template <int KDIM, int EPI>
__global__ __launch_bounds__(256) void gemm_bf(
    const __nv_bfloat16* __restrict__ Ahg, const __nv_bfloat16* __restrict__ Alg,
    const __nv_bfloat16* __restrict__ Whg, const __nv_bfloat16* __restrict__ Wlg,
    const float* __restrict__ bias, float* __restrict__ C)
{
    __shared__ __align__(16) __nv_bfloat16 Ash[2][128 * SSTR];
    __shared__ __align__(16) __nv_bfloat16 Wsh[2][128 * SSTR];
    __shared__ float s_bn[2 * 128];   // EPI2: per-block column sum / sumsq
    const int tid = threadIdx.x;
    const int lane = tid & 31;
    const int wid = tid >> 5;
    const int wr = wid & 3;         // warp row (0..3) -> 32 rows
    const int wcq = wid >> 2;       // warp col (0..1) -> 64 cols
    const int lq = lane & 3;
    const int lg = lane >> 2;
    const int row0 = blockIdx.x * 128;
    const int col0 = blockIdx.y * 128;

    if (EPI == 2) {
        if (tid < 256) { s_bn[tid] = 0.f; }
    }

    float acc[2][8][4];
#pragma unroll
    for (int mt = 0; mt < 2; mt++)
#pragma unroll
        for (int nt = 0; nt < 8; nt++)
#pragma unroll
            for (int j = 0; j < 4; j++) acc[mt][nt][j] = 0.f;

    // ldmatrix per-lane address offsets (element units)
    const unsigned offA = ((lane & 7) + ((lane >> 3) & 1) * 8) * SSTR
                        + ((lane >> 4) & 1) * 8;
    const unsigned offW = (lane & 7) * SSTR + ((lane >> 3) & 1) * 8;
    const unsigned aB0 = (unsigned)__cvta_generic_to_shared(&Ash[0][0]);
    const unsigned aB1 = (unsigned)__cvta_generic_to_shared(&Ash[1][0]);
    const unsigned wB0 = (unsigned)__cvta_generic_to_shared(&Wsh[0][0]);
    const unsigned wB1 = (unsigned)__cvta_generic_to_shared(&Wsh[1][0]);

    const int lr = tid >> 1;            // 0..127: tile row (A) / col (W)
    const int hf = (tid & 1) * 16;      // 16-elem half of the 32-k slab

    for (int k0 = 0; k0 < KDIM; k0 += 32) {
        // A tile copy: each thread covers 16 bf16 = 2x uint4 per plane
        uint4 vh0 = make_uint4(0u,0u,0u,0u), vh1 = vh0, vl0 = vh0, vl1 = vh0;
        long grow = row0 + lr;
        if (grow < NN) {
            const __nv_bfloat16* pa = &Ahg[grow * KDIM + k0 + hf];
            const __nv_bfloat16* pl = &Alg[grow * KDIM + k0 + hf];
            vh0 = *(const uint4*)pa;
            vh1 = *(const uint4*)(pa + 8);
            vl0 = *(const uint4*)pl;
            vl1 = *(const uint4*)(pl + 8);
        }
        *(uint4*)&Ash[0][lr * SSTR + hf]     = vh0;
        *(uint4*)&Ash[0][lr * SSTR + hf + 8] = vh1;
        *(uint4*)&Ash[1][lr * SSTR + hf]     = vl0;
        *(uint4*)&Ash[1][lr * SSTR + hf + 8] = vl1;
        {
            long gcol = col0 + lr;
            const __nv_bfloat16* pw = &Whg[gcol * KDIM + k0 + hf];
            const __nv_bfloat16* pq = &Wlg[gcol * KDIM + k0 + hf];
            *(uint4*)&Wsh[0][lr * SSTR + hf]     = *(const uint4*)pw;
            *(uint4*)&Wsh[0][lr * SSTR + hf + 8] = *(const uint4*)(pw + 8);
            *(uint4*)&Wsh[1][lr * SSTR + hf]     = *(const uint4*)pq;
            *(uint4*)&Wsh[1][lr * SSTR + hf + 8] = *(const uint4*)(pq + 8);
        }
        __syncthreads();

#pragma unroll
        for (int ks = 0; ks < 2; ks++) {
            unsigned ah[2][4], al[2][4];
#pragma unroll
            for (int mt = 0; mt < 2; mt++) {
                unsigned ra = ((wr * 32 + mt * 16) * SSTR + ks * 16 + offA) * 2;
                ldsm_x4(ah[mt], aB0 + ra);
                ldsm_x4(al[mt], aB1 + ra);
            }
#pragma unroll
            for (int nt = 0; nt < 8; nt++) {
                unsigned rw = ((wcq * 64 + nt * 8) * SSTR + ks * 16 + offW) * 2;
                unsigned bh0, bh1, bl0, bl1;
                ldsm_x2(bh0, bh1, wB0 + rw);
                ldsm_x2(bl0, bl1, wB1 + rw);
#pragma unroll
                for (int mt = 0; mt < 2; mt++) {
                    mma_bf16(acc[mt][nt], ah[mt], bh0, bh1);  // hi*hi
                    mma_bf16(acc[mt][nt], al[mt], bh0, bh1);  // lo*hi
                    mma_bf16(acc[mt][nt], ah[mt], bl0, bl1);  // hi*lo
                }
            }
        }
        __syncthreads();
    }

    // ---------------- epilogue ----------------
#pragma unroll
    for (int nt = 0; nt < 8; nt++) {
        int c = col0 + wcq * 64 + nt * 8 + 2 * lq;
        float2 bb = *(const float2*)&bias[c];
        float ps0 = 0.f, ps1 = 0.f, pq0 = 0.f, pq1 = 0.f;
#pragma unroll
        for (int mt = 0; mt < 2; mt++) {
            int r = row0 + wr * 32 + mt * 16 + lg;  // rows r, r+8
            float* a = acc[mt][nt];
            if (EPI == 0) {
#pragma unroll
                for (int half = 0; half < 2; half++) {
                    int row = r + half * 8;
                    if (row >= NN) continue;
                    float z0 = tanhf(a[half * 2 + 0] + bb.x);
                    float z1 = tanhf(a[half * 2 + 1] + bb.y);
                    __nv_bfloat162 h2, l2;
                    bsplit(z0, h2.x, l2.x);
                    bsplit(z1, h2.y, l2.y);
                    ((__nv_bfloat162*)g_zh)[(row * DH + c) >> 1] = h2;
                    ((__nv_bfloat162*)g_zl)[(row * DH + c) >> 1] = l2;
                }
            } else if (EPI == 1) {
                if (r < NN)
                    *(float2*)&C[r * DH + c] = make_float2(a[0] + bb.x, a[1] + bb.y);
                if (r + 8 < NN)
                    *(float2*)&C[(r + 8) * DH + c] = make_float2(a[2] + bb.x, a[3] + bb.y);
            } else {
#pragma unroll
                for (int half = 0; half < 2; half++) {
                    int row = r + half * 8;
                    if (row >= NN) continue;
                    float2 xl = *(const float2*)&g_xl[row * DH + c];
                    __nv_bfloat162 zh2 = ((const __nv_bfloat162*)g_zh)[(row * DH + c) >> 1];
                    __nv_bfloat162 zl2 = ((const __nv_bfloat162*)g_zl)[(row * DH + c) >> 1];
                    float z0 = __bfloat162float(zh2.x) + __bfloat162float(zl2.x);
                    float z1 = __bfloat162float(zh2.y) + __bfloat162float(zl2.y);
                    float g0 = 1.f / (1.f + __expf(-(a[half * 2 + 0] + bb.x)));
                    float g1 = 1.f / (1.f + __expf(-(a[half * 2 + 1] + bb.y)));
                    float o0 = fmaxf((1.f - g0) * xl.x + g0 * z0, 0.f);
                    float o1 = fmaxf((1.f - g1) * xl.y + g1 * z1, 0.f);
                    *(float2*)&C[row * DH + c] = make_float2(o0, o1);
                    ps0 += o0; pq0 += o0 * o0;
                    ps1 += o1; pq1 += o1 * o1;
                }
            }
        }
        if (EPI == 2) {
            int cl = wcq * 64 + nt * 8 + 2 * lq;
            atomicAdd(&s_bn[cl], ps0);
            atomicAdd(&s_bn[cl + 1], ps1);
            atomicAdd(&s_bn[128 + cl], pq0);
            atomicAdd(&s_bn[128 + cl + 1], pq1);
        }
    }
    if (EPI == 2) {
        __syncthreads();
        if (tid < 128) {
            atomicAdd(&g_colsum[col0 + tid], s_bn[tid]);
            atomicAdd(&g_colsq[col0 + tid], s_bn[128 + tid]);
        }
    }
}

// ---------------- batch-norm finalize ----------------------------------------
__global__ void bnstats_kernel(const float* __restrict__ gamma,
                               const float* __restrict__ beta) {
    int c = threadIdx.x;
    float mu = g_colsum[c] * (1.f / NN);
    float var = g_colsq[c] * (1.f / NN) - mu * mu;
    float rstd = rsqrtf(var + 1e-5f);
    float sc = rstd * gamma[c];
    g_scale[c] = sc;
    g_shift[c] = beta[c] - mu * sc;
}

__global__ void bnapply_kernel(float* __restrict__ out) {
    int i = blockIdx.x * blockDim.x + threadIdx.x;
    if (i >= NN * DH / 4) return;
    int c = (i & (DH / 4 - 1)) * 4;
    float4 v = ((float4*)out)[i];
    v.x = v.x * g_scale[c + 0] + g_shift[c + 0];
    v.y = v.y * g_scale[c + 1] + g_shift[c + 1];
    v.z = v.z * g_scale[c + 2] + g_shift[c + 2];
    v.w = v.w * g_scale[c + 3] + g_shift[c + 3];
    ((float4*)out)[i] = v;
}

// ---------------- launch -----------------------------------------------------
template <typename T>
static T* symp(const void* sym) {
    void* p = nullptr;
    cudaGetSymbolAddress(&p, sym);
    return (T*)p;
}

extern "C" void kernel_launch(void* const* d_in, const int* in_sizes, int n_in,
                              void* d_out, int out_size) {
    const float* xs     = (const float*)d_in[0];
    const void*  ei     = d_in[1];
    const float* W_gcn  = (const float*)d_in[2];
    const float* b_gcn  = (const float*)d_in[3];
    const float* W_lin  = (const float*)d_in[4];
    const float* b_lin  = (const float*)d_in[5];
    const float* W_gate = (const float*)d_in[6];
    const float* b_gate = (const float*)d_in[7];
    const float* gamma  = (const float*)d_in[8];
    const float* beta   = (const float*)d_in[9];
    float* out = (float*)d_out;

    float* p_xl = symp<float>(g_xl);
    __nv_bfloat16* p_xsh = symp<__nv_bfloat16>(g_xsh);
    __nv_bfloat16* p_xsl = symp<__nv_bfloat16>(g_xsl);
    __nv_bfloat16* p_xah = symp<__nv_bfloat16>(g_xah);
    __nv_bfloat16* p_xal = symp<__nv_bfloat16>(g_xal);
    __nv_bfloat16* p_zh  = symp<__nv_bfloat16>(g_zh);
    __nv_bfloat16* p_zl  = symp<__nv_bfloat16>(g_zl);
    __nv_bfloat16* p_wch = symp<__nv_bfloat16>(g_wch);
    __nv_bfloat16* p_wcl = symp<__nv_bfloat16>(g_wcl);
    __nv_bfloat16* p_wlh = symp<__nv_bfloat16>(g_wlh);
    __nv_bfloat16* p_wll = symp<__nv_bfloat16>(g_wll);
    __nv_bfloat16* p_wgh = symp<__nv_bfloat16>(g_wgh);
    __nv_bfloat16* p_wgl = symp<__nv_bfloat16>(g_wgl);

    init_kernel<<<(NN + 255) / 256, 256>>>();
    detect_kernel<<<1, 32>>>(ei);
    deg_kernel<<<(NE + 255) / 256, 256>>>(ei);
    dinv_kernel<<<(NN + 255) / 256, 256>>>();
    scan_kernel<<<1, 1024>>>();
    scatter_kernel<<<(NE + 255) / 256, 256>>>(ei);

    wsplit_kernel<<<(2 * DH * DI + DH * DH + 255) / 256, 256>>>(W_gcn, W_lin, W_gate);
    xsplit_kernel<<<(NN * DI / 4 + 255) / 256, 256>>>(xs);

    aggx_kernel<<<(NN + 7) / 8, 256>>>(xs);

    dim3 gg((NN + 127) / 128, 2);
    gemm_bf<DI, 0><<<gg, 256>>>(p_xah, p_xal, p_wch, p_wcl, b_gcn, nullptr);
    gemm_bf<DI, 1><<<gg, 256>>>(p_xsh, p_xsl, p_wlh, p_wll, b_lin, p_xl);
    gemm_bf<DH, 2><<<gg, 256>>>(p_zh, p_zl, p_wgh, p_wgl, b_gate, out);

    bnstats_kernel<<<1, DH>>>(gamma, beta);
    bnapply_kernel<<<(NN * DH / 4 + 255) / 256, 256>>>(out);
}

// round 14
// speedup vs baseline: 1.1845x; 1.1845x over previous
#include <cuda_runtime.h>
#include <cuda_bf16.h>
#include <math.h>

#define NN 50000
#define NE 800000
#define DI 64
#define DH 256

// ---------------- scratch (device globals) -----------------------------------
__device__ float g_xl[NN * DH];     // xs @ W_lin + b_lin
__device__ float g_z[NN * DH];      // tanh(xagg @ W_gcn + b_gcn)
__device__ __align__(16) __nv_bfloat16 g_xsh[NN * DI];   // xs hi  [row][k]
__device__ __align__(16) __nv_bfloat16 g_xsl[NN * DI];   // xs lo
__device__ __align__(16) __nv_bfloat16 g_xah[NN * DI];   // xagg hi [row][k]
__device__ __align__(16) __nv_bfloat16 g_xal[NN * DI];
__device__ __align__(16) __nv_bfloat16 g_zh[NN * DH];    // z hi [row][k]
__device__ __align__(16) __nv_bfloat16 g_zl[NN * DH];
__device__ __align__(16) __nv_bfloat16 g_wch[DH * DI];   // W_gcn  [col][k]
__device__ __align__(16) __nv_bfloat16 g_wcl[DH * DI];
__device__ __align__(16) __nv_bfloat16 g_wlh[DH * DI];   // W_lin  [col][k]
__device__ __align__(16) __nv_bfloat16 g_wll[DH * DI];
__device__ __align__(16) __nv_bfloat16 g_wgh[DH * DH];   // W_gate [col][k]
__device__ __align__(16) __nv_bfloat16 g_wgl[DH * DH];
__device__ int   g_deg[NN];
__device__ float g_dinv[NN];
__device__ int   g_rowptr[NN + 1];
__device__ int   g_fill[NN];
__device__ int   g_srcsorted[NE];
__device__ float g_colsum[DH];
__device__ float g_colsq[DH];
__device__ float g_scale[DH];
__device__ float g_shift[DH];
__device__ int   g_is64;

__device__ __forceinline__ void bsplit(float x, __nv_bfloat16& h, __nv_bfloat16& l) {
    h = __float2bfloat16(x);
    l = __float2bfloat16(x - __bfloat162float(h));
}

// ---------------- small kernels ----------------------------------------------
__global__ void init_kernel() {
    int i = blockIdx.x * blockDim.x + threadIdx.x;
    if (i < NN) { g_deg[i] = 0; g_fill[i] = 0; }
    if (i < DH) { g_colsum[i] = 0.f; g_colsq[i] = 0.f; }
}

__global__ void detect_kernel(const void* ei) {
    if (threadIdx.x == 0 && blockIdx.x == 0) {
        const long long* p = (const long long*)ei;
        int ok = 1;
        for (int i = 0; i < 64; i++) {
            long long v = p[i];
            if (v < 0 || v >= NN) ok = 0;
        }
        g_is64 = ok;
    }
}

__device__ __forceinline__ int load_edge(const void* ei, int pos, int is64) {
    return is64 ? (int)((const long long*)ei)[pos] : ((const int*)ei)[pos];
}

__global__ void deg_kernel(const void* __restrict__ ei) {
    int e = blockIdx.x * blockDim.x + threadIdx.x;
    if (e >= NE) return;
    int d = load_edge(ei, NE + e, g_is64);
    atomicAdd(&g_deg[d], 1);
}

__global__ void dinv_kernel() {
    int i = blockIdx.x * blockDim.x + threadIdx.x;
    if (i < NN) g_dinv[i] = rsqrtf((float)(g_deg[i] + 1));
}

__global__ void scan_kernel() {
    __shared__ int s[1024];
    int t = threadIdx.x;
    const int C = (NN + 1023) / 1024;
    int start = t * C;
    int end = min(start + C, NN);
    int sum = 0;
    for (int i = start; i < end; i++) sum += g_deg[i];
    s[t] = sum;
    __syncthreads();
    for (int off = 1; off < 1024; off <<= 1) {
        int v = (t >= off) ? s[t - off] : 0;
        __syncthreads();
        s[t] += v;
        __syncthreads();
    }
    int run = s[t] - sum;
    for (int i = start; i < end; i++) { g_rowptr[i] = run; run += g_deg[i]; }
    if (t == 0) g_rowptr[NN] = s[1023];
}

__global__ void scatter_kernel(const void* __restrict__ ei) {
    int e = blockIdx.x * blockDim.x + threadIdx.x;
    if (e >= NE) return;
    int is64 = g_is64;
    int d = load_edge(ei, NE + e, is64);
    int srcv = load_edge(ei, e, is64);
    int pos = g_rowptr[d] + atomicAdd(&g_fill[d], 1);
    g_srcsorted[pos] = srcv;
}

// ---------------- weight / input pre-splitting -------------------------------
__global__ void wsplit_kernel(const float* __restrict__ Wc,
                              const float* __restrict__ Wl,
                              const float* __restrict__ Wg) {
    int i = blockIdx.x * blockDim.x + threadIdx.x;
    const int NW1 = DH * DI;
    if (i < 2 * NW1) {
        int sel = i / NW1;
        int j = i - sel * NW1;
        int c = j / DI, k = j - c * DI;
        float x = (sel ? Wl : Wc)[k * DH + c];
        __nv_bfloat16 h, l;
        bsplit(x, h, l);
        if (sel) { g_wlh[j] = h; g_wll[j] = l; }
        else     { g_wch[j] = h; g_wcl[j] = l; }
    } else {
        int j = i - 2 * NW1;
        if (j >= DH * DH) return;
        int c = j / DH, k = j - c * DH;
        float x = Wg[k * DH + c];
        __nv_bfloat16 h, l;
        bsplit(x, h, l);
        g_wgh[j] = h; g_wgl[j] = l;
    }
}

__global__ void xsplit_kernel(const float* __restrict__ xs) {
    int i = blockIdx.x * blockDim.x + threadIdx.x;  // float4 index
    if (i >= NN * DI / 4) return;
    float4 v = ((const float4*)xs)[i];
    __nv_bfloat162 h0, l0, h1, l1;
    bsplit(v.x, h0.x, l0.x); bsplit(v.y, h0.y, l0.y);
    bsplit(v.z, h1.x, l1.x); bsplit(v.w, h1.y, l1.y);
    ((__nv_bfloat162*)g_xsh)[i * 2] = h0;
    ((__nv_bfloat162*)g_xsh)[i * 2 + 1] = h1;
    ((__nv_bfloat162*)g_xsl)[i * 2] = l0;
    ((__nv_bfloat162*)g_xsl)[i * 2 + 1] = l1;
}

// ---------------- 64-dim aggregation (warp per node, CSR) --------------------
__global__ __launch_bounds__(256) void aggx_kernel(const float* __restrict__ xs) {
    int w = (blockIdx.x * 256 + threadIdx.x) >> 5;
    int lane = threadIdx.x & 31;
    if (w >= NN) return;
    int beg = g_rowptr[w];
    int end = g_rowptr[w + 1];
    const float2* xs2 = (const float2*)xs;
    float2 acc = make_float2(0.f, 0.f);
    for (int k = beg; k < end; k++) {
        int s = g_srcsorted[k];
        float wt = g_dinv[s];
        float2 v = xs2[s * 32 + lane];
        acc.x += v.x * wt;
        acc.y += v.y * wt;
    }
    float di = g_dinv[w];
    float2 xv = xs2[w * 32 + lane];
    float rx = acc.x * di + xv.x * di * di;
    float ry = acc.y * di + xv.y * di * di;
    __nv_bfloat162 h2, l2;
    bsplit(rx, h2.x, l2.x);
    bsplit(ry, h2.y, l2.y);
    ((__nv_bfloat162*)g_xah)[w * 32 + lane] = h2;
    ((__nv_bfloat162*)g_xal)[w * 32 + lane] = l2;
}

// ---------------- bf16 split-3 tensor-core GEMM + cp.async pipeline ----------
// C[M x 256] = A[M x KDIM] @ W[KDIM x 256]
// A pre-split bf16 hi/lo [row][KDIM]; W pre-split bf16 [col][KDIM].
// EPI 0: z = tanh(acc + b_gcn) -> g_z fp32 + g_zh/g_zl bf16 split
// EPI 1: C = acc + bias
// EPI 2: g = sigmoid(acc + b_gate); C = relu((1-g)*xl + g*z)

__device__ __forceinline__ void mma_bf16(float c[4], const unsigned a[4],
                                         unsigned b0, unsigned b1) {
    asm volatile(
        "mma.sync.aligned.m16n8k16.row.col.f32.bf16.bf16.f32 "
        "{%0,%1,%2,%3},{%4,%5,%6,%7},{%8,%9},{%0,%1,%2,%3};\n"
        : "+f"(c[0]), "+f"(c[1]), "+f"(c[2]), "+f"(c[3])
        : "r"(a[0]), "r"(a[1]), "r"(a[2]), "r"(a[3]), "r"(b0), "r"(b1));
}

__device__ __forceinline__ void cpa16(unsigned dst, const void* src, bool p) {
    int sz = p ? 16 : 0;
    asm volatile("cp.async.cg.shared.global [%0], [%1], 16, %2;"
                 :: "r"(dst), "l"(src), "r"(sz));
}

#define SSTR 40                    // smem row stride (elems); conflict-free
#define PLANE_E (128 * SSTR)       // 5120 elems per plane
#define PLANE_B (PLANE_E * 2)      // 10240 bytes
#define STAGE_E (4 * PLANE_E)      // Ah, Al, Wh, Wl
#define STAGE_B (4 * PLANE_B)      // 40960 bytes
#define SMEM_TOTAL (2 * STAGE_B)   // 81920 bytes

extern __shared__ __align__(16) __nv_bfloat16 sm_dyn[];

template <int KDIM, int EPI>
__global__ __launch_bounds__(256) void gemm_bf(
    const __nv_bfloat16* __restrict__ Ahg, const __nv_bfloat16* __restrict__ Alg,
    const __nv_bfloat16* __restrict__ Whg, const __nv_bfloat16* __restrict__ Wlg,
    const float* __restrict__ bias, float* __restrict__ C)
{
    const int tid = threadIdx.x;
    const int lane = tid & 31;
    const int wid = tid >> 5;
    const int wr = wid & 3;         // warp row (0..3) -> 32 rows
    const int wcq = wid >> 2;       // warp col (0..1) -> 64 cols
    const int lq = lane & 3;
    const int lg = lane >> 2;
    const int row0 = blockIdx.x * 128;
    const int col0 = blockIdx.y * 128;

    float acc[2][8][4];
#pragma unroll
    for (int mt = 0; mt < 2; mt++)
#pragma unroll
        for (int nt = 0; nt < 8; nt++)
#pragma unroll
            for (int j = 0; j < 4; j++) acc[mt][nt][j] = 0.f;

    const int lr = tid >> 1;            // 0..127: tile row (A) / col (W)
    const int hf = (tid & 1) * 16;      // 16-elem half of the 32-k slab
    const unsigned smem_u32 = (unsigned)__cvta_generic_to_shared(sm_dyn);

    const int T = KDIM / 32;
    const bool okA0 = (row0 + lr) < NN;
    const long arow = (long)(okA0 ? row0 + lr : 0) * KDIM + hf;
    const long wrow = (long)(col0 + lr) * KDIM + hf;
    const unsigned d0 = (lr * SSTR + hf) * 2;
    const unsigned d1 = (lr * SSTR + hf + 8) * 2;

    // issue one 32-k tile into stage st
    auto issue = [&](int itx, int st) {
        const long ko = itx * 32;
        const unsigned base = smem_u32 + st * STAGE_B;
        cpa16(base + d0,               Ahg + arow + ko,     okA0);
        cpa16(base + d1,               Ahg + arow + ko + 8, okA0);
        cpa16(base + PLANE_B + d0,     Alg + arow + ko,     okA0);
        cpa16(base + PLANE_B + d1,     Alg + arow + ko + 8, okA0);
        cpa16(base + 2 * PLANE_B + d0, Whg + wrow + ko,     true);
        cpa16(base + 2 * PLANE_B + d1, Whg + wrow + ko + 8, true);
        cpa16(base + 3 * PLANE_B + d0, Wlg + wrow + ko,     true);
        cpa16(base + 3 * PLANE_B + d1, Wlg + wrow + ko + 8, true);
        asm volatile("cp.async.commit_group;");
    };

    issue(0, 0);

    for (int it = 0; it < T; it++) {
        if (it + 1 < T) {
            issue(it + 1, (it + 1) & 1);
            asm volatile("cp.async.wait_group 1;" ::: "memory");
        } else {
            asm volatile("cp.async.wait_group 0;" ::: "memory");
        }
        __syncthreads();

        const __nv_bfloat16* Ah = sm_dyn + (it & 1) * STAGE_E;
        const __nv_bfloat16* Al = Ah + PLANE_E;
        const __nv_bfloat16* Wh = Ah + 2 * PLANE_E;
        const __nv_bfloat16* Wl = Ah + 3 * PLANE_E;

#pragma unroll
        for (int ks = 0; ks < 2; ks++) {
            const int kb = ks * 16;
            unsigned ah[2][4], al[2][4];
#pragma unroll
            for (int mt = 0; mt < 2; mt++) {
                int rb = wr * 32 + mt * 16 + lg;
                ah[mt][0] = *(const unsigned*)&Ah[rb * SSTR + kb + 2 * lq];
                ah[mt][1] = *(const unsigned*)&Ah[(rb + 8) * SSTR + kb + 2 * lq];
                ah[mt][2] = *(const unsigned*)&Ah[rb * SSTR + kb + 8 + 2 * lq];
                ah[mt][3] = *(const unsigned*)&Ah[(rb + 8) * SSTR + kb + 8 + 2 * lq];
                al[mt][0] = *(const unsigned*)&Al[rb * SSTR + kb + 2 * lq];
                al[mt][1] = *(const unsigned*)&Al[(rb + 8) * SSTR + kb + 2 * lq];
                al[mt][2] = *(const unsigned*)&Al[rb * SSTR + kb + 8 + 2 * lq];
                al[mt][3] = *(const unsigned*)&Al[(rb + 8) * SSTR + kb + 8 + 2 * lq];
            }
#pragma unroll
            for (int nt = 0; nt < 8; nt++) {
                int cb = wcq * 64 + nt * 8 + lg;
                unsigned bh0 = *(const unsigned*)&Wh[cb * SSTR + kb + 2 * lq];
                unsigned bh1 = *(const unsigned*)&Wh[cb * SSTR + kb + 8 + 2 * lq];
                unsigned bl0 = *(const unsigned*)&Wl[cb * SSTR + kb + 2 * lq];
                unsigned bl1 = *(const unsigned*)&Wl[cb * SSTR + kb + 8 + 2 * lq];
#pragma unroll
                for (int mt = 0; mt < 2; mt++) {
                    mma_bf16(acc[mt][nt], ah[mt], bh0, bh1);  // hi*hi
                    mma_bf16(acc[mt][nt], al[mt], bh0, bh1);  // lo*hi
                    mma_bf16(acc[mt][nt], ah[mt], bl0, bl1);  // hi*lo
                }
            }
        }
        __syncthreads();
    }

    // ---------------- epilogue ----------------
#pragma unroll
    for (int mt = 0; mt < 2; mt++) {
        int r = row0 + wr * 32 + mt * 16 + lg;  // rows r, r+8
#pragma unroll
        for (int nt = 0; nt < 8; nt++) {
            int c = col0 + wcq * 64 + nt * 8 + 2 * lq;
            float* a = acc[mt][nt];
            float2 bb = *(const float2*)&bias[c];
            if (EPI == 0) {
#pragma unroll
                for (int half = 0; half < 2; half++) {
                    int row = r + half * 8;
                    if (row >= NN) continue;
                    float z0 = tanhf(a[half * 2 + 0] + bb.x);
                    float z1 = tanhf(a[half * 2 + 1] + bb.y);
                    *(float2*)&C[row * DH + c] = make_float2(z0, z1);
                    __nv_bfloat162 h2, l2;
                    bsplit(z0, h2.x, l2.x);
                    bsplit(z1, h2.y, l2.y);
                    ((__nv_bfloat162*)g_zh)[(row * DH + c) >> 1] = h2;
                    ((__nv_bfloat162*)g_zl)[(row * DH + c) >> 1] = l2;
                }
            } else if (EPI == 1) {
                if (r < NN)
                    *(float2*)&C[r * DH + c] = make_float2(a[0] + bb.x, a[1] + bb.y);
                if (r + 8 < NN)
                    *(float2*)&C[(r + 8) * DH + c] = make_float2(a[2] + bb.x, a[3] + bb.y);
            } else {
#pragma unroll
                for (int half = 0; half < 2; half++) {
                    int row = r + half * 8;
                    if (row >= NN) continue;
                    float2 xl = *(const float2*)&g_xl[row * DH + c];
                    float2 zz = *(const float2*)&g_z[row * DH + c];
                    float g0 = 1.f / (1.f + __expf(-(a[half * 2 + 0] + bb.x)));
                    float g1 = 1.f / (1.f + __expf(-(a[half * 2 + 1] + bb.y)));
                    float o0 = fmaxf((1.f - g0) * xl.x + g0 * zz.x, 0.f);
                    float o1 = fmaxf((1.f - g1) * xl.y + g1 * zz.y, 0.f);
                    *(float2*)&C[row * DH + c] = make_float2(o0, o1);
                }
            }
        }
    }
}

// ---------------- batch-norm -------------------------------------------------
__global__ void bnreduce_kernel(const float* __restrict__ out) {
    int c = threadIdx.x;
    int r0 = blockIdx.x * 128;
    int rend = min(r0 + 128, NN);
    float s = 0.f, q = 0.f;
    for (int r = r0; r < rend; r++) {
        float v = out[r * DH + c];
        s += v;
        q += v * v;
    }
    atomicAdd(&g_colsum[c], s);
    atomicAdd(&g_colsq[c], q);
}

__global__ void bnstats_kernel(const float* __restrict__ gamma,
                               const float* __restrict__ beta) {
    int c = threadIdx.x;
    float mu = g_colsum[c] * (1.f / NN);
    float var = g_colsq[c] * (1.f / NN) - mu * mu;
    float rstd = rsqrtf(var + 1e-5f);
    float sc = rstd * gamma[c];
    g_scale[c] = sc;
    g_shift[c] = beta[c] - mu * sc;
}

__global__ void bnapply_kernel(float* __restrict__ out) {
    int i = blockIdx.x * blockDim.x + threadIdx.x;
    if (i >= NN * DH / 4) return;
    int c = (i & (DH / 4 - 1)) * 4;
    float4 v = ((float4*)out)[i];
    v.x = v.x * g_scale[c + 0] + g_shift[c + 0];
    v.y = v.y * g_scale[c + 1] + g_shift[c + 1];
    v.z = v.z * g_scale[c + 2] + g_shift[c + 2];
    v.w = v.w * g_scale[c + 3] + g_shift[c + 3];
    ((float4*)out)[i] = v;
}

// ---------------- launch -----------------------------------------------------
template <typename T>
static T* symp(const void* sym) {
    void* p = nullptr;
    cudaGetSymbolAddress(&p, sym);
    return (T*)p;
}

extern "C" void kernel_launch(void* const* d_in, const int* in_sizes, int n_in,
                              void* d_out, int out_size) {
    const float* xs     = (const float*)d_in[0];
    const void*  ei     = d_in[1];
    const float* W_gcn  = (const float*)d_in[2];
    const float* b_gcn  = (const float*)d_in[3];
    const float* W_lin  = (const float*)d_in[4];
    const float* b_lin  = (const float*)d_in[5];
    const float* W_gate = (const float*)d_in[6];
    const float* b_gate = (const float*)d_in[7];
    const float* gamma  = (const float*)d_in[8];
    const float* beta   = (const float*)d_in[9];
    float* out = (float*)d_out;

    float* p_xl = symp<float>(g_xl);
    float* p_z  = symp<float>(g_z);
    __nv_bfloat16* p_xsh = symp<__nv_bfloat16>(g_xsh);
    __nv_bfloat16* p_xsl = symp<__nv_bfloat16>(g_xsl);
    __nv_bfloat16* p_xah = symp<__nv_bfloat16>(g_xah);
    __nv_bfloat16* p_xal = symp<__nv_bfloat16>(g_xal);
    __nv_bfloat16* p_zh  = symp<__nv_bfloat16>(g_zh);
    __nv_bfloat16* p_zl  = symp<__nv_bfloat16>(g_zl);
    __nv_bfloat16* p_wch = symp<__nv_bfloat16>(g_wch);
    __nv_bfloat16* p_wcl = symp<__nv_bfloat16>(g_wcl);
    __nv_bfloat16* p_wlh = symp<__nv_bfloat16>(g_wlh);
    __nv_bfloat16* p_wll = symp<__nv_bfloat16>(g_wll);
    __nv_bfloat16* p_wgh = symp<__nv_bfloat16>(g_wgh);
    __nv_bfloat16* p_wgl = symp<__nv_bfloat16>(g_wgl);

    static bool attr_done = false;
    if (!attr_done) {
        cudaFuncSetAttribute(gemm_bf<DI, 0>,
            cudaFuncAttributeMaxDynamicSharedMemorySize, SMEM_TOTAL);
        cudaFuncSetAttribute(gemm_bf<DI, 1>,
            cudaFuncAttributeMaxDynamicSharedMemorySize, SMEM_TOTAL);
        cudaFuncSetAttribute(gemm_bf<DH, 2>,
            cudaFuncAttributeMaxDynamicSharedMemorySize, SMEM_TOTAL);
        attr_done = true;
    }

    init_kernel<<<(NN + 255) / 256, 256>>>();
    detect_kernel<<<1, 32>>>(ei);
    deg_kernel<<<(NE + 255) / 256, 256>>>(ei);
    dinv_kernel<<<(NN + 255) / 256, 256>>>();
    scan_kernel<<<1, 1024>>>();
    scatter_kernel<<<(NE + 255) / 256, 256>>>(ei);

    wsplit_kernel<<<(2 * DH * DI + DH * DH + 255) / 256, 256>>>(W_gcn, W_lin, W_gate);
    xsplit_kernel<<<(NN * DI / 4 + 255) / 256, 256>>>(xs);

    aggx_kernel<<<(NN + 7) / 8, 256>>>(xs);

    dim3 gg((NN + 127) / 128, 2);
    gemm_bf<DI, 0><<<gg, 256, SMEM_TOTAL>>>(p_xah, p_xal, p_wch, p_wcl, b_gcn, p_z);
    gemm_bf<DI, 1><<<gg, 256, SMEM_TOTAL>>>(p_xsh, p_xsl, p_wlh, p_wll, b_lin, p_xl);
    gemm_bf<DH, 2><<<gg, 256, SMEM_TOTAL>>>(p_zh, p_zl, p_wgh, p_wgl, b_gate, out);

    bnreduce_kernel<<<(NN + 127) / 128, 256>>>(out);
    bnstats_kernel<<<1, DH>>>(gamma, beta);
    bnapply_kernel<<<(NN * DH / 4 + 255) / 256, 256>>>(out);
}